// round 16
// baseline (speedup 1.0000x reference)
#include <cuda_runtime.h>
#include <cuda_bf16.h>
#include <cstdint>

#define BB    2048
#define CC    9605
#define LL    8
#define NT    256
#define TOPK  16
#define TVAL  2.6f
#define CAP   1024
#define NW    (NT / 32)
#define DEPTH 3                 // cp.async pipeline stages
#define STB   (NT * 16)         // stage bytes per tensor (256 packs x 16B)

#define ALPHA   0.5f
#define ALPHA1  0.05f
#define ALPHA2  2.0f
#define ALPHA3  5.0f
#define ALPHA_OTHER 0.3f

// Scratch (no cudaMalloc allowed)
__device__ float          g_partial[BB];
__device__ unsigned char  g_gbits[CC + 16];
__device__ unsigned short g_glist[LL * CC];  // group-major class lists (UNORDERED)
__device__ int            g_gcnt[LL];        // zero-init; reset by row_kernel tail
__device__ int            g_done;            // zero-init; reset by row_kernel tail

__device__ __forceinline__ float sigm(float v) { return 1.0f / (1.0f + __expf(-v)); }

__device__ __forceinline__ float rankl(float x1, float x2) {
    float d = x2 - x1 + ALPHA1;
    float s = 1.0f / (1.0f + __expf(-ALPHA3 * d));
    return d > 0.0f ? ALPHA2 * s : s;
}

__device__ __forceinline__ void cpa16(void* smem, const void* gmem) {
    unsigned a = (unsigned)__cvta_generic_to_shared(smem);
    asm volatile("cp.async.cg.shared.global [%0], [%1], 16;" :: "r"(a), "l"(gmem));
}
#define CP_COMMIT() asm volatile("cp.async.commit_group;" ::: "memory")
#define CP_WAIT()   asm volatile("cp.async.wait_group %0;" :: "n"(DEPTH - 1) : "memory")

// ---------------------------------------------------------------------------
// prep (ONE launch, multi-block): each block redundantly classifies the mask
// dtype (uint4 scan), then builds its slice of membership bytes + UNORDERED
// group-major compaction via atomic counters.
//   f32 1.0 -> bytes {00,00,80,3F}: some byte has a bit above bit0 -> word mode
//   i32 1   -> ones only at offset%4==0                            -> word mode
//   bool    -> 0x01 at arbitrary byte offsets                      -> byte mode
// ---------------------------------------------------------------------------
__global__ __launch_bounds__(1024) void prep_kernel(const unsigned char* __restrict__ mraw) {
    __shared__ int s_gt1, s_mis;
    const int t = threadIdx.x;
    if (t == 0) { s_gt1 = 0; s_mis = 0; }
    __syncthreads();

    const uint4* m4 = (const uint4*)mraw;
    const unsigned int* mw = (const unsigned int*)mraw;
    unsigned int a = 0, bm = 0;
    for (int i = t; i < 4802; i += 1024) {     // 19210 words = 4802 uint4 + 2
        uint4 v = __ldg(m4 + i);
        unsigned int o = v.x | v.y | v.z | v.w;
        a  |= (o & 0xFEFEFEFEu);
        bm |= (o & 0x01010100u);
    }
    if (t < 2) {
        unsigned int v = __ldg(mw + 19208 + t);
        a  |= (v & 0xFEFEFEFEu);
        bm |= (v & 0x01010100u);
    }
    if (a)  atomicOr(&s_gt1, 1);
    if (bm) atomicOr(&s_mis, 1);
    __syncthreads();
    const int bytemode = (!s_gt1) && s_mis;

    int c = blockIdx.x * 1024 + t;
    if (c >= CC) return;
    unsigned int bits = 0;
    if (bytemode) {
        #pragma unroll
        for (int l = 0; l < LL; ++l)
            if (mraw[l * CC + c] != 0) bits |= (1u << l);
    } else {
        #pragma unroll
        for (int l = 0; l < LL; ++l)
            if (mw[l * CC + c] != 0u) bits |= (1u << l);
    }
    g_gbits[c] = (unsigned char)bits;
    #pragma unroll
    for (int l = 0; l < LL; ++l) {
        if (bits & (1u << l)) {
            int pos = atomicAdd(&g_gcnt[l], 1);
            g_glist[l * CC + pos] = (unsigned short)c;
        }
    }
}

// ---------------------------------------------------------------------------
// row_kernel: one CTA per sample.
// Loop 1: cp.async (LDGSTS) 3-stage pipeline streams x/y/yn global->smem —
//   in-flight bytes live in smem, not registers. Each thread writes and reads
//   ONLY its own 16B slots of each stage buffer, so no block barriers are
//   needed inside the pipeline: each warp self-paces on its own wait_group.
//   Candidate detection via pack-max + divergent atomic append; y/yn positives
//   via integer-OR test. Remainder packs + peel/tail use direct loads.
// Loop 2: group-major x-only gathers (L2-hot): 1 fmax per entry.
// Selection: order-invariant rank-count over candidates (exact, deterministic).
// Last CTA reduces partials deterministically and resets g_gcnt/g_done.
// ---------------------------------------------------------------------------
__global__ __launch_bounds__(NT) void row_kernel(const float* __restrict__ x,
                                                 const float* __restrict__ y,
                                                 const float* __restrict__ yn,
                                                 float* __restrict__ out) {
    __shared__ alignas(16) unsigned char s_buf[DEPTH][3][STB];   // 36 KB
    __shared__ float s_cand[CAP];
    __shared__ float s_red[NT];
    __shared__ float s_gmax[NW][LL];
    __shared__ unsigned int s_gtb[NW], s_gnb[NW];
    __shared__ float s_t16;
    __shared__ int s_ncand, s_last;

    const int b = blockIdx.x, t = threadIdx.x, w = t >> 5, lane = t & 31;
    const size_t base = (size_t)b * CC;
    const float* __restrict__ xr = x + base;
    const float* __restrict__ yr = y + base;
    const float* __restrict__ nr = yn + base;

    // alignment: (b*9605) % 4 == b % 4; after peel the packed base is 16B-aligned
    const int av = b & 3;
    const int p  = (4 - av) & 3;             // scalar peel count
    const int nv = (CC - p) >> 2;            // float4 count
    const int r  = (CC - p) & 3;             // scalar tail count

    if (t == 0) s_ncand = 0;
    __syncthreads();

    const float NI = __int_as_float(0xff800000);
    const unsigned fm = 0xFFFFFFFFu;
    unsigned int gtb = 0, gnb = 0;

    // ---- peel + tail (<= 5 elements; scalar, no collectives) ----
    if (t < p + r) {
        int idx = (t < p) ? t : (p + 4 * nv + (t - p));
        float xv = __ldg(xr + idx);
        if (xv > TVAL) {
            int pos = atomicAdd(&s_ncand, 1);
            if (pos < CAP) s_cand[pos] = xv;
        }
        unsigned int gb = g_gbits[idx];
        if (gb) {
            if (__ldg(yr + idx) > 0.0f) gtb |= gb;
            if (__ldg(nr + idx) > 0.0f) gnb |= gb;
        }
    }

    const float4* __restrict__ x4 = (const float4*)(xr + p);
    const uint4*  __restrict__ yu = (const uint4*)(yr + p);
    const uint4*  __restrict__ nu = (const uint4*)(nr + p);

    // candidate append: pack-max gate, then divergent atomic (rare)
    #define XBLK(XV)                                                           \
    {                                                                          \
        float _pm = fmaxf(fmaxf((XV).x, (XV).y), fmaxf((XV).z, (XV).w));       \
        if (_pm > TVAL) {                                                      \
            int _c = ((XV).x > TVAL) + ((XV).y > TVAL) +                       \
                     ((XV).z > TVAL) + ((XV).w > TVAL);                        \
            int _pos = atomicAdd(&s_ncand, _c);                                \
            if ((XV).x > TVAL) { if (_pos < CAP) s_cand[_pos] = (XV).x; ++_pos; } \
            if ((XV).y > TVAL) { if (_pos < CAP) s_cand[_pos] = (XV).y; ++_pos; } \
            if ((XV).z > TVAL) { if (_pos < CAP) s_cand[_pos] = (XV).z; ++_pos; } \
            if ((XV).w > TVAL) { if (_pos < CAP) s_cand[_pos] = (XV).w; ++_pos; } \
        }                                                                      \
    }

    // positive detection on binarized y/yn: nonzero bit pattern <=> 1.0f
    #define YBLK(YV, VI, DST)                                                  \
    {                                                                          \
        if (((YV).x | (YV).y | (YV).z | (YV).w) != 0u) {                       \
            int _ci = p + 4 * (VI);                                            \
            if ((YV).x) DST |= (unsigned int)g_gbits[_ci];                     \
            if ((YV).y) DST |= (unsigned int)g_gbits[_ci + 1];                 \
            if ((YV).z) DST |= (unsigned int)g_gbits[_ci + 2];                 \
            if ((YV).w) DST |= (unsigned int)g_gbits[_ci + 3];                 \
        }                                                                      \
    }

    // ---- Loop 1: cp.async 3-stage pipeline over full stages of NT packs ----
    const int nstages = nv / NT;             // 9 full stages; rem < NT packs

    // prologue: issue DEPTH-1 stages (commit each, even if short)
    #pragma unroll
    for (int s = 0; s < DEPTH - 1; ++s) {
        if (s < nstages) {
            int pk = s * NT + t;
            cpa16(&s_buf[s][0][t * 16], x4 + pk);
            cpa16(&s_buf[s][1][t * 16], yu + pk);
            cpa16(&s_buf[s][2][t * 16], nu + pk);
        }
        CP_COMMIT();
    }

    for (int s = 0; s < nstages; ++s) {
        const int si = s + DEPTH - 1;
        if (si < nstages) {
            const int bi = si % DEPTH;
            int pk = si * NT + t;
            cpa16(&s_buf[bi][0][t * 16], x4 + pk);
            cpa16(&s_buf[bi][1][t * 16], yu + pk);
            cpa16(&s_buf[bi][2][t * 16], nu + pk);
        }
        CP_COMMIT();                         // uniform group count (empty ok)
        CP_WAIT();                           // stage s complete for THIS thread

        // per-thread slot ownership: no block barrier needed
        const int bi = s % DEPTH;
        const int pk = s * NT + t;
        float4 xa = *(const float4*)&s_buf[bi][0][t * 16];
        uint4  ya = *(const uint4*)&s_buf[bi][1][t * 16];
        uint4  na = *(const uint4*)&s_buf[bi][2][t * 16];
        XBLK(xa)
        YBLK(ya, pk, gtb)
        YBLK(na, pk, gnb)
    }

    // remainder packs (< NT): direct loads, one pack per thread
    {
        const int v = nstages * NT + t;
        if (v < nv) {
            float4 xa = __ldg(x4 + v);
            uint4  ya = __ldcs(yu + v);
            uint4  na = __ldcs(nu + v);
            XBLK(xa)
            YBLK(ya, v, gtb)
            YBLK(na, v, gnb)
        }
    }
    #undef XBLK
    #undef YBLK

    // ---- Loop 2: group-major x gathers (L2-hot), 1 fmax per entry ----
    float gmax[LL];
    #pragma unroll
    for (int l = 0; l < LL; ++l) {
        const int cnt = __ldg(&g_gcnt[l]);
        const unsigned short* __restrict__ lst = g_glist + l * CC;
        float m = NI;
        for (int i = t; i < cnt; i += NT)
            m = fmaxf(m, __ldg(xr + (int)__ldg(lst + i)));
        gmax[l] = m;
    }

    // ---- warp-reduce aggregates ----
    #pragma unroll
    for (int off = 16; off > 0; off >>= 1) {
        #pragma unroll
        for (int l = 0; l < LL; ++l)
            gmax[l] = fmaxf(gmax[l], __shfl_xor_sync(fm, gmax[l], off));
        gtb |= __shfl_xor_sync(fm, gtb, off);
        gnb |= __shfl_xor_sync(fm, gnb, off);
    }
    if (lane == 0) {
        #pragma unroll
        for (int l = 0; l < LL; ++l) s_gmax[w][l] = gmax[l];
        s_gtb[w] = gtb;
        s_gnb[w] = gnb;
    }
    __syncthreads();

    int nc = s_ncand;                            // true count of x > TVAL

    // ---- exact fallback (data-independent guarantee): rebuild candidates ----
    if (nc < TOPK || nc > CAP) {
        __syncthreads();                         // everyone done reading s_ncand
        if (t < 64) {
            float tk[TOPK];
            #pragma unroll
            for (int k = 0; k < TOPK; ++k) tk[k] = NI;
            for (int i = t; i < CC; i += 64) {
                float xv = __ldg(xr + i);
                if (xv > tk[TOPK - 1]) {
                    float _v = xv;
                    #pragma unroll
                    for (int k = 0; k < TOPK; ++k)
                        if (_v > tk[k]) { float _tmp = tk[k]; tk[k] = _v; _v = _tmp; }
                }
            }
            #pragma unroll
            for (int k = 0; k < TOPK; ++k) s_cand[t * TOPK + k] = tk[k];
        }
        __syncthreads();
        nc = 64 * TOPK;                          // row top-16 is within these 1024
    }

    // ---- rank-count selection: 16th-largest = v with #{>v} <= 15 < #{>=v} ----
    for (int i = t; i < nc; i += NT) {
        float v = s_cand[i];
        int cg = 0, ce = 0;
        for (int j = 0; j < nc; ++j) {
            float u = s_cand[j];                 // broadcast read, conflict-free
            cg += (u > v);
            ce += (u == v);
        }
        if (cg <= TOPK - 1 && cg + ce >= TOPK) s_t16 = v;   // unique value; benign race
    }
    __syncthreads();

    // ---- per-row loss (thread 0) ----
    if (t == 0) {
        float gmaxA[LL];
        #pragma unroll
        for (int l = 0; l < LL; ++l) gmaxA[l] = NI;
        unsigned int gtA = 0, gnA = 0;
        for (int wv = 0; wv < NW; ++wv) {
            #pragma unroll
            for (int l = 0; l < LL; ++l) gmaxA[l] = fmaxf(gmaxA[l], s_gmax[wv][l]);
            gtA |= s_gtb[wv];
            gnA |= s_gnb[wv];
        }
        float umaxA = NI;                        // union max = max over group maxes
        #pragma unroll
        for (int l = 0; l < LL; ++l) umaxA = fmaxf(umaxA, gmaxA[l]);

        float thres = fmaxf(sigm(s_t16), ALPHA_OTHER);

        float loss;
        if (gtA) {
            loss = 0.0f;
            #pragma unroll
            for (int l = 0; l < LL; ++l) {
                float gm = sigm(gmaxA[l]);
                loss += ((gtA >> l) & 1u) ? rankl(gm, thres)
                                          : rankl(thres, gm);
            }
        } else {
            float um = sigm(umaxA);
            float negs = 0.0f;                   // torch starts at 0
            if (gnA) {
                float nm = NI;
                #pragma unroll
                for (int l = 0; l < LL; ++l)
                    if ((gnA >> l) & 1u) nm = fmaxf(nm, gmaxA[l]);
                negs = sigm(nm);
            }
            loss = (1.0f - ALPHA) * rankl(thres, um) + ALPHA * rankl(thres, negs);
        }
        g_partial[b] = loss;
    }

    // ---- fused deterministic mean: last CTA reduces; resets counters ----
    if (t == 0) {
        __threadfence();
        int old = atomicAdd(&g_done, 1);
        s_last = (old == BB - 1);
    }
    __syncthreads();
    if (s_last) {
        float acc = 0.0f;
        for (int i = t; i < BB; i += NT) acc += g_partial[i];   // fixed order
        s_red[t] = acc;
        __syncthreads();
        for (int st = NT / 2; st > 0; st >>= 1) {
            if (t < st) s_red[t] += s_red[t + st];
            __syncthreads();
        }
        if (t == 0) { out[0] = s_red[0] / (float)BB; g_done = 0; }
        if (t < LL) g_gcnt[t] = 0;               // safe: all CTAs past loop 2
    }
}

extern "C" void kernel_launch(void* const* d_in, const int* in_sizes, int n_in,
                              void* d_out, int out_size) {
    (void)in_sizes; (void)n_in; (void)out_size;
    const float*         x  = (const float*)d_in[0];
    const float*         y  = (const float*)d_in[1];
    const float*         yn = (const float*)d_in[2];
    const unsigned char* m  = (const unsigned char*)d_in[3];

    prep_kernel<<<(CC + 1023) / 1024, 1024>>>(m);
    row_kernel<<<BB, NT>>>(x, y, yn, (float*)d_out);
}

// round 17
// speedup vs baseline: 1.6230x; 1.6230x over previous
#include <cuda_runtime.h>
#include <cuda_bf16.h>
#include <cstdint>

#define BB    2048
#define CC    9605
#define LL    8
#define NT    256
#define GRID  740               // 148 SMs x 5 CTAs: persistent
#define TOPK  16
#define TVAL  2.6f
#define CAP   1024
#define NW    (NT / 32)

#define ALPHA   0.5f
#define ALPHA1  0.05f
#define ALPHA2  2.0f
#define ALPHA3  5.0f
#define ALPHA_OTHER 0.3f

// Scratch (no cudaMalloc allowed)
__device__ float          g_partial[BB];
__device__ unsigned char  g_gbits[CC + 16];
__device__ unsigned short g_glist[LL * CC];  // group-major class lists (UNORDERED)
__device__ int            g_gcnt[LL];        // zero-init; reset by row_kernel tail
__device__ int            g_done;            // zero-init; reset by row_kernel tail

__device__ __forceinline__ float sigm(float v) { return 1.0f / (1.0f + __expf(-v)); }

__device__ __forceinline__ float rankl(float x1, float x2) {
    float d = x2 - x1 + ALPHA1;
    float s = 1.0f / (1.0f + __expf(-ALPHA3 * d));
    return d > 0.0f ? ALPHA2 * s : s;
}

// ---------------------------------------------------------------------------
// prep (ONE launch, multi-block): each block redundantly classifies the mask
// dtype (uint4 scan), then builds its slice of membership bytes + UNORDERED
// group-major compaction via atomic counters.
//   f32 1.0 -> bytes {00,00,80,3F}: some byte has a bit above bit0 -> word mode
//   i32 1   -> ones only at offset%4==0                            -> word mode
//   bool    -> 0x01 at arbitrary byte offsets                      -> byte mode
// ---------------------------------------------------------------------------
__global__ __launch_bounds__(1024) void prep_kernel(const unsigned char* __restrict__ mraw) {
    __shared__ int s_gt1, s_mis;
    const int t = threadIdx.x;
    if (t == 0) { s_gt1 = 0; s_mis = 0; }
    __syncthreads();

    const uint4* m4 = (const uint4*)mraw;
    const unsigned int* mw = (const unsigned int*)mraw;
    unsigned int a = 0, bm = 0;
    for (int i = t; i < 4802; i += 1024) {     // 19210 words = 4802 uint4 + 2
        uint4 v = __ldg(m4 + i);
        unsigned int o = v.x | v.y | v.z | v.w;
        a  |= (o & 0xFEFEFEFEu);
        bm |= (o & 0x01010100u);
    }
    if (t < 2) {
        unsigned int v = __ldg(mw + 19208 + t);
        a  |= (v & 0xFEFEFEFEu);
        bm |= (v & 0x01010100u);
    }
    if (a)  atomicOr(&s_gt1, 1);
    if (bm) atomicOr(&s_mis, 1);
    __syncthreads();
    const int bytemode = (!s_gt1) && s_mis;

    int c = blockIdx.x * 1024 + t;
    if (c >= CC) return;
    unsigned int bits = 0;
    if (bytemode) {
        #pragma unroll
        for (int l = 0; l < LL; ++l)
            if (mraw[l * CC + c] != 0) bits |= (1u << l);
    } else {
        #pragma unroll
        for (int l = 0; l < LL; ++l)
            if (mw[l * CC + c] != 0u) bits |= (1u << l);
    }
    g_gbits[c] = (unsigned char)bits;
    #pragma unroll
    for (int l = 0; l < LL; ++l) {
        if (bits & (1u << l)) {
            int pos = atomicAdd(&g_gcnt[l], 1);
            g_glist[l * CC + pos] = (unsigned short)c;
        }
    }
}

// ---------------------------------------------------------------------------
// row_kernel: persistent — GRID CTAs each loop over rows b += GRID.
// Loop 1: coalesced stream (x float4, y/yn uint4; 2 packs/iter, 6 loads with
//   clamped second index). Candidate detection via pack-max + divergent
//   atomic append; y/yn positives via integer-OR test (binarized inputs).
// Loop 2: ONE round of 8 CONCURRENT per-group gathers (counts < NT in
//   practice; while-loop for generality) — collapses 8 serialized L2 round
//   trips into ~1. Counts packed 2-per-u32, hoisted per CTA.
// Selection: order-invariant rank-count over candidates (exact, deterministic).
// Tail: last of GRID CTAs reduces the 2048 partials; resets g_gcnt/g_done.
// ---------------------------------------------------------------------------
__global__ __launch_bounds__(NT, 5) void row_kernel(const float* __restrict__ x,
                                                    const float* __restrict__ y,
                                                    const float* __restrict__ yn,
                                                    float* __restrict__ out) {
    __shared__ float s_cand[CAP];
    __shared__ float s_red[NT];
    __shared__ float s_gmax[NW][LL];
    __shared__ unsigned int s_gtb[NW], s_gnb[NW];
    __shared__ float s_t16;
    __shared__ int s_ncand, s_last;

    const int t = threadIdx.x, w = t >> 5, lane = t & 31;
    const float NI = __int_as_float(0xff800000);
    const unsigned fm = 0xFFFFFFFFu;

    // per-CTA: pack the 8 group counts into 4 u32 (hi16|lo16) + max count
    int maxc;
    unsigned int cp01, cp23, cp45, cp67;
    {
        int c0 = __ldg(&g_gcnt[0]), c1 = __ldg(&g_gcnt[1]);
        int c2 = __ldg(&g_gcnt[2]), c3 = __ldg(&g_gcnt[3]);
        int c4 = __ldg(&g_gcnt[4]), c5 = __ldg(&g_gcnt[5]);
        int c6 = __ldg(&g_gcnt[6]), c7 = __ldg(&g_gcnt[7]);
        cp01 = (unsigned)c0 | ((unsigned)c1 << 16);
        cp23 = (unsigned)c2 | ((unsigned)c3 << 16);
        cp45 = (unsigned)c4 | ((unsigned)c5 << 16);
        cp67 = (unsigned)c6 | ((unsigned)c7 << 16);
        maxc = max(max(max(c0, c1), max(c2, c3)), max(max(c4, c5), max(c6, c7)));
    }
    #define CNT(L) (int)(((L) & 1 ? (((L) < 2 ? cp01 : (L) < 4 ? cp23 : (L) < 6 ? cp45 : cp67) >> 16) \
                                  : (((L) < 2 ? cp01 : (L) < 4 ? cp23 : (L) < 6 ? cp45 : cp67))) & 0xFFFFu)

    for (int b = blockIdx.x; b < BB; b += GRID) {
        __syncthreads();                         // prior row fully consumed
        if (t == 0) s_ncand = 0;
        __syncthreads();

        const size_t base = (size_t)b * CC;
        const float* __restrict__ xr = x + base;
        const float* __restrict__ yr = y + base;
        const float* __restrict__ nr = yn + base;

        // alignment: (b*9605) % 4 == b % 4  (9605 % 4 == 1)
        const int av = b & 3;
        const int p  = (4 - av) & 3;             // scalar peel count
        const int nv = (CC - p) >> 2;            // float4 count
        const int r  = (CC - p) & 3;             // scalar tail count

        unsigned int gtb = 0, gnb = 0;

        // ---- peel + tail (<= 5 elements; scalar, no collectives) ----
        if (t < p + r) {
            int idx = (t < p) ? t : (p + 4 * nv + (t - p));
            float xv = __ldg(xr + idx);
            if (xv > TVAL) {
                int pos = atomicAdd(&s_ncand, 1);
                if (pos < CAP) s_cand[pos] = xv;
            }
            unsigned int gb = g_gbits[idx];
            if (gb) {
                if (__ldg(yr + idx) > 0.0f) gtb |= gb;
                if (__ldg(nr + idx) > 0.0f) gnb |= gb;
            }
        }

        const float4* __restrict__ x4 = (const float4*)(xr + p);
        const uint4*  __restrict__ yu = (const uint4*)(yr + p);
        const uint4*  __restrict__ nu = (const uint4*)(nr + p);

        #define XBLK(XV)                                                           \
        {                                                                          \
            float _pm = fmaxf(fmaxf((XV).x, (XV).y), fmaxf((XV).z, (XV).w));       \
            if (_pm > TVAL) {                                                      \
                int _c = ((XV).x > TVAL) + ((XV).y > TVAL) +                       \
                         ((XV).z > TVAL) + ((XV).w > TVAL);                        \
                int _pos = atomicAdd(&s_ncand, _c);                                \
                if ((XV).x > TVAL) { if (_pos < CAP) s_cand[_pos] = (XV).x; ++_pos; } \
                if ((XV).y > TVAL) { if (_pos < CAP) s_cand[_pos] = (XV).y; ++_pos; } \
                if ((XV).z > TVAL) { if (_pos < CAP) s_cand[_pos] = (XV).z; ++_pos; } \
                if ((XV).w > TVAL) { if (_pos < CAP) s_cand[_pos] = (XV).w; ++_pos; } \
            }                                                                      \
        }
        #define YBLK(YV, VI, DST)                                                  \
        {                                                                          \
            if (((YV).x | (YV).y | (YV).z | (YV).w) != 0u) {                       \
                int _ci = p + 4 * (VI);                                            \
                if ((YV).x) DST |= (unsigned int)g_gbits[_ci];                     \
                if ((YV).y) DST |= (unsigned int)g_gbits[_ci + 1];                 \
                if ((YV).z) DST |= (unsigned int)g_gbits[_ci + 2];                 \
                if ((YV).w) DST |= (unsigned int)g_gbits[_ci + 3];                 \
            }                                                                      \
        }

        // ---- Loop 1: coalesced stream, 2 packs/iter, 6 unconditional loads ----
        for (int v = t; v < nv; v += 2 * NT) {
            const int vb = v + NT;
            const bool hb = (vb < nv);
            const int vbc = hb ? vb : v;         // clamped: load always legal
            float4 xa = __ldg(x4 + v);
            float4 xb = __ldg(x4 + vbc);
            uint4  ya = __ldcs(yu + v);
            uint4  yb = __ldcs(yu + vbc);
            uint4  na = __ldcs(nu + v);
            uint4  nb = __ldcs(nu + vbc);

            XBLK(xa)
            YBLK(ya, v, gtb)
            YBLK(na, v, gnb)
            if (hb) {
                XBLK(xb)
                YBLK(yb, vb, gtb)
                YBLK(nb, vb, gnb)
            }
        }
        #undef XBLK
        #undef YBLK

        // ---- Loop 2: 8 groups gathered CONCURRENTLY per round (1 round typ.) ----
        float gmax[LL];
        #pragma unroll
        for (int l = 0; l < LL; ++l) gmax[l] = NI;

        for (int basei = 0; basei < maxc; basei += NT) {
            const int i = basei + t;
            #pragma unroll
            for (int l = 0; l < LL; ++l) {
                const int cl = CNT(l);
                const int act = (i < cl);
                int raw = (int)__ldg(&g_glist[l * CC + (act ? i : 0)]);
                float v = __ldg(xr + (act ? raw : 0));      // clamped: in-bounds
                if (act) gmax[l] = fmaxf(gmax[l], v);
            }
        }

        // ---- warp-reduce aggregates ----
        #pragma unroll
        for (int off = 16; off > 0; off >>= 1) {
            #pragma unroll
            for (int l = 0; l < LL; ++l)
                gmax[l] = fmaxf(gmax[l], __shfl_xor_sync(fm, gmax[l], off));
            gtb |= __shfl_xor_sync(fm, gtb, off);
            gnb |= __shfl_xor_sync(fm, gnb, off);
        }
        if (lane == 0) {
            #pragma unroll
            for (int l = 0; l < LL; ++l) s_gmax[w][l] = gmax[l];
            s_gtb[w] = gtb;
            s_gnb[w] = gnb;
        }
        __syncthreads();

        int nc = s_ncand;                        // true count of x > TVAL

        // ---- exact fallback (data-independent guarantee) ----
        if (nc < TOPK || nc > CAP) {
            __syncthreads();
            if (t < 64) {
                float tk[TOPK];
                #pragma unroll
                for (int k = 0; k < TOPK; ++k) tk[k] = NI;
                for (int i = t; i < CC; i += 64) {
                    float xv = __ldg(xr + i);
                    if (xv > tk[TOPK - 1]) {
                        float _v = xv;
                        #pragma unroll
                        for (int k = 0; k < TOPK; ++k)
                            if (_v > tk[k]) { float _tmp = tk[k]; tk[k] = _v; _v = _tmp; }
                    }
                }
                #pragma unroll
                for (int k = 0; k < TOPK; ++k) s_cand[t * TOPK + k] = tk[k];
            }
            __syncthreads();
            nc = 64 * TOPK;                      // row top-16 is within these 1024
        }

        // ---- rank-count: 16th-largest = v with #{>v} <= 15 < #{>=v} ----
        for (int i = t; i < nc; i += NT) {
            float v = s_cand[i];
            int cg = 0, ce = 0;
            for (int j = 0; j < nc; ++j) {
                float u = s_cand[j];             // broadcast read, conflict-free
                cg += (u > v);
                ce += (u == v);
            }
            if (cg <= TOPK - 1 && cg + ce >= TOPK) s_t16 = v;  // unique; benign race
        }
        __syncthreads();

        // ---- per-row loss (thread 0) ----
        if (t == 0) {
            float gmaxA[LL];
            #pragma unroll
            for (int l = 0; l < LL; ++l) gmaxA[l] = NI;
            unsigned int gtA = 0, gnA = 0;
            for (int wv = 0; wv < NW; ++wv) {
                #pragma unroll
                for (int l = 0; l < LL; ++l) gmaxA[l] = fmaxf(gmaxA[l], s_gmax[wv][l]);
                gtA |= s_gtb[wv];
                gnA |= s_gnb[wv];
            }
            float umaxA = NI;                    // union max = max over group maxes
            #pragma unroll
            for (int l = 0; l < LL; ++l) umaxA = fmaxf(umaxA, gmaxA[l]);

            float thres = fmaxf(sigm(s_t16), ALPHA_OTHER);

            float loss;
            if (gtA) {
                loss = 0.0f;
                #pragma unroll
                for (int l = 0; l < LL; ++l) {
                    float gm = sigm(gmaxA[l]);
                    loss += ((gtA >> l) & 1u) ? rankl(gm, thres)
                                              : rankl(thres, gm);
                }
            } else {
                float um = sigm(umaxA);
                float negs = 0.0f;               // torch starts at 0
                if (gnA) {
                    float nm = NI;
                    #pragma unroll
                    for (int l = 0; l < LL; ++l)
                        if ((gnA >> l) & 1u) nm = fmaxf(nm, gmaxA[l]);
                    negs = sigm(nm);
                }
                loss = (1.0f - ALPHA) * rankl(thres, um) + ALPHA * rankl(thres, negs);
            }
            g_partial[b] = loss;
        }
    }
    #undef CNT

    // ---- tail: last of GRID CTAs reduces all partials; resets counters ----
    if (t == 0) {
        __threadfence();
        int old = atomicAdd(&g_done, 1);
        s_last = (old == GRID - 1);
    }
    __syncthreads();
    if (s_last) {
        float acc = 0.0f;
        for (int i = t; i < BB; i += NT) acc += g_partial[i];   // fixed order
        s_red[t] = acc;
        __syncthreads();
        for (int st = NT / 2; st > 0; st >>= 1) {
            if (t < st) s_red[t] += s_red[t + st];
            __syncthreads();
        }
        if (t == 0) { out[0] = s_red[0] / (float)BB; g_done = 0; }
        if (t < LL) g_gcnt[t] = 0;               // safe: all CTAs past loop 2
    }
}

extern "C" void kernel_launch(void* const* d_in, const int* in_sizes, int n_in,
                              void* d_out, int out_size) {
    (void)in_sizes; (void)n_in; (void)out_size;
    const float*         x  = (const float*)d_in[0];
    const float*         y  = (const float*)d_in[1];
    const float*         yn = (const float*)d_in[2];
    const unsigned char* m  = (const unsigned char*)d_in[3];

    prep_kernel<<<(CC + 1023) / 1024, 1024>>>(m);
    row_kernel<<<GRID, NT>>>(x, y, yn, (float*)d_out);
}